// round 9
// baseline (speedup 1.0000x reference)
#include <cuda_runtime.h>
#include <cuda_bf16.h>
#include <math.h>
#include <stdint.h>

#define B_    256
#define T_    128
#define NIN   700
#define H_    2048

// ---------------- device scratch ----------------
__device__ float         g_U [(size_t)B_ * T_ * H_];    // 0.5*(x@W+bias)
__device__ __nv_bfloat16 gA0 [(size_t)H_ * H_];         // A^T splits [n][k]
__device__ __nv_bfloat16 gA1 [(size_t)H_ * H_];
__device__ __nv_bfloat16 gA2 [(size_t)H_ * H_];
__device__ __nv_bfloat16 gS  [2][(size_t)B_ * H_];      // spike ping-pong (exact 0/1)

// ---------------- asm helpers (sm_80+ portable) ----------------
__device__ __forceinline__ uint32_t smem_u32(const void* p) {
    uint32_t a;
    asm("{ .reg .u64 t; cvta.to.shared.u64 t, %1; cvt.u32.u64 %0, t; }"
        : "=r"(a) : "l"(p));
    return a;
}
__device__ __forceinline__ void cpa16(uint32_t dst, const void* src) {
    asm volatile("cp.async.cg.shared.global [%0], [%1], 16;"
                 :: "r"(dst), "l"(src) : "memory");
}
// zfill variant: src_size 0 -> 16 bytes of zeros (exact +0 contributions)
__device__ __forceinline__ void cpa16_z(uint32_t dst, const void* src, bool v) {
    uint32_t sz = v ? 16u : 0u;
    asm volatile("cp.async.cg.shared.global [%0], [%1], 16, %2;"
                 :: "r"(dst), "l"(src), "r"(sz) : "memory");
}
#define CP_COMMIT() asm volatile("cp.async.commit_group;" ::: "memory")
#define CP_WAIT0()  asm volatile("cp.async.wait_group 0;" ::: "memory")
#define CP_WAIT1()  asm volatile("cp.async.wait_group 1;" ::: "memory")
#define CP_WAIT4()  asm volatile("cp.async.wait_group 4;" ::: "memory")

__device__ __forceinline__ void ldsm4(uint32_t* r, uint32_t a) {
    asm volatile("ldmatrix.sync.aligned.m8n8.x4.shared.b16 {%0,%1,%2,%3}, [%4];"
                 : "=r"(r[0]), "=r"(r[1]), "=r"(r[2]), "=r"(r[3]) : "r"(a));
}
__device__ __forceinline__ void mma16816(float* c, const uint32_t* a,
                                         const uint32_t* b) {
    asm volatile("mma.sync.aligned.m16n8k16.row.col.f32.bf16.bf16.f32 "
                 "{%0,%1,%2,%3}, {%4,%5,%6,%7}, {%8,%9}, {%0,%1,%2,%3};"
                 : "+f"(c[0]), "+f"(c[1]), "+f"(c[2]), "+f"(c[3])
                 : "r"(a[0]), "r"(a[1]), "r"(a[2]), "r"(a[3]),
                   "r"(b[0]), "r"(b[1]));
}

// ---------------- bf16 3-way exact split ----------------
__device__ __forceinline__ void split3(float v, __nv_bfloat16& b0,
                                       __nv_bfloat16& b1, __nv_bfloat16& b2) {
    b0 = __float2bfloat16(v);
    float f0 = __bfloat162float(b0);
    b1 = __float2bfloat16(v - f0);
    float f1 = __bfloat162float(b1);
    b2 = __float2bfloat16(v - f0 - f1);
}

__global__ void k_split_A(const float* __restrict__ A) {
    __shared__ float tile[32][33];
    int tx = threadIdx.x, ty = threadIdx.y;
    int kbase = blockIdx.y * 32, nbase = blockIdx.x * 32;
    #pragma unroll
    for (int i = 0; i < 32; i += 8)
        tile[ty + i][tx] = A[(size_t)(kbase + ty + i) * H_ + nbase + tx];
    __syncthreads();
    #pragma unroll
    for (int i = 0; i < 32; i += 8) {
        float v = tile[tx][ty + i];
        size_t o = (size_t)(nbase + ty + i) * H_ + kbase + tx;
        __nv_bfloat16 b0, b1, b2; split3(v, b0, b1, b2);
        gA0[o] = b0; gA1[o] = b1; gA2[o] = b2;
    }
}

// ------- input GEMM: fp32, ascending-k FFMA order (bit-identical to R1), ---
// ------- BK=16 + cp.async double buffer -----------------------------------
__global__ void __launch_bounds__(256) k_input_gemm(
    const float* __restrict__ X, const float* __restrict__ W,
    const float* __restrict__ bias)
{
    constexpr int K = NIN, N = H_;
    constexpr int BM = 128, BN = 128, BK = 16, TM = 8, TN = 8;
    __shared__ __align__(16) float As[2][BM][BK];   // 8KB x2
    __shared__ __align__(16) float Bs[2][BK][BN];   // 8KB x2

    const int tid = threadIdx.x;
    const int bm = blockIdx.y, bn = blockIdx.x;
    const int tRow = (tid >> 4) << 3, tCol = (tid & 15) << 3;
    const int m0g = bm * BM, n0g = bn * BN;

    // A chunks: 512 float4 (row=c>>2, koff=(c&3)*4); B chunks: 512 float4
    auto load_stage = [&](int buf, int k0) {
        #pragma unroll
        for (int h = 0; h < 2; h++) {
            int c = tid + h * 256;
            int ar = c >> 2, aj = (c & 3) * 4;
            cpa16_z(smem_u32(&As[buf][ar][aj]),
                    X + (size_t)(m0g + ar) * K + k0 + aj, (k0 + aj) < K);
            int brw = c >> 5, bc = (c & 31) * 4;
            cpa16_z(smem_u32(&Bs[buf][brw][bc]),
                    W + (size_t)(k0 + brw) * N + n0g + bc, (k0 + brw) < K);
        }
    };

    float acc[TM][TN];
    #pragma unroll
    for (int i = 0; i < TM; i++)
        #pragma unroll
        for (int j = 0; j < TN; j++) acc[i][j] = 0.f;

    constexpr int NS = (K + BK - 1) / BK;   // 44
    load_stage(0, 0); CP_COMMIT();

    for (int s = 0; s < NS; s++) {
        int buf = s & 1;
        __syncthreads();                      // prev consumers done before overwrite
        if (s + 1 < NS) { load_stage(buf ^ 1, (s + 1) * BK); CP_COMMIT(); CP_WAIT1(); }
        else CP_WAIT0();
        __syncthreads();

        #pragma unroll
        for (int k = 0; k < BK; k++) {
            float aF[TM], bF[TN];
            #pragma unroll
            for (int i = 0; i < TM; i++) aF[i] = As[buf][tRow + i][k];
            float4 b0 = *(const float4*)&Bs[buf][k][tCol];
            float4 b1 = *(const float4*)&Bs[buf][k][tCol + 4];
            bF[0] = b0.x; bF[1] = b0.y; bF[2] = b0.z; bF[3] = b0.w;
            bF[4] = b1.x; bF[5] = b1.y; bF[6] = b1.z; bF[7] = b1.w;
            #pragma unroll
            for (int i = 0; i < TM; i++)
                #pragma unroll
                for (int j = 0; j < TN; j++) acc[i][j] += aF[i] * bF[j];
        }
    }

    const int m0 = m0g + tRow, n0 = n0g + tCol;
    #pragma unroll
    for (int i = 0; i < TM; i++) {
        size_t row = (size_t)(m0 + i) * N;
        #pragma unroll
        for (int j = 0; j < TN; j++)
            g_U[row + n0 + j] = 0.5f * (acc[i][j] + bias[n0 + j]);
    }
}

// ---------------- frame 0 (spike0 = 0 -> r = 0) ----------------
__global__ void k_frame0(const float* __restrict__ mem_init,
                         float* __restrict__ out_mems,
                         float* __restrict__ out_spikes)
{
    size_t idx = (size_t)blockIdx.x * 256 + threadIdx.x;
    int b = (int)(idx / H_), n = (int)(idx % H_);
    size_t o = ((size_t)b * T_) * H_ + n;
    float u = g_U[o];
    float y = tanhf(u);
    float mem = mem_init[idx] * 0.5f - 0.5f * (1.0f - 0.0f) + y;
    float sp = (mem > 0.5f) ? 1.0f : 0.0f;
    out_mems[o] = mem;
    out_spikes[o] = sp;
    gS[0][idx] = __float2bfloat16(sp);
}

// ==== recurrent frame: 3-term exact bf16 mma, chunked fold =================
// BM=64, BN=32 -> 256 CTAs (~2/SM). 256 threads, 8 warps (4m x 2n),
// warp tile 16m x 16n. 6-stage cp.async ring. Per-element accumulation order
// BIT-IDENTICAL to rounds 6/8 (BK=32 chunks; kk -> p -> ni chain; IEEE fold).
#define SPD 40                              // padded row stride (bf16 elems)
#define ST_SPK (64 * SPD)                   // 2560 elems
#define ST_A   (32 * SPD)                   // 1280 elems
#define ST_EL  (ST_SPK + 3 * ST_A)          // 6400 elems = 12800 B
#define FR_STAGES 6
#define FR_SMEM_B (FR_STAGES * ST_EL * 2)   // 76800 B

__global__ void __launch_bounds__(256)
k_frame_mma(float* __restrict__ out_mems, float* __restrict__ out_spikes, int t)
{
    extern __shared__ __align__(16) __nv_bfloat16 smf[];
    const int tid = threadIdx.x;
    const int lane = tid & 31, w = tid >> 5;      // 8 warps
    const int wm = w & 3, wn = w >> 2;            // warp tile 16(m) x 16(n)
    const int l15 = lane & 15;
    const int n0 = blockIdx.x * 32, m0 = blockIdx.y * 64;

    const __nv_bfloat16* Sg = gS[(t + 1) & 1];
    const __nv_bfloat16* Ap[3] = { gA0 + (size_t)n0 * H_,
                                   gA1 + (size_t)n0 * H_,
                                   gA2 + (size_t)n0 * H_ };

    // stage = spike 64x32 + 3x A 32x32 = 640 x 16B chunks
    auto load_stage = [&](int buf, int k0) {
        __nv_bfloat16* st = smf + (size_t)buf * ST_EL;
        for (int c = tid; c < 640; c += 256) {
            if (c < 256) {
                int r = c >> 2, j = (c & 3) * 8;
                cpa16(smem_u32(st + r * SPD + j),
                      Sg + (size_t)(m0 + r) * H_ + k0 + j);
            } else {
                int c2 = c - 256;
                int p = c2 >> 7, r = (c2 & 127) >> 2, j = (c2 & 3) * 8;
                cpa16(smem_u32(st + ST_SPK + p * ST_A + r * SPD + j),
                      Ap[p] + (size_t)r * H_ + k0 + j);
            }
        }
    };

    float master[2][4];
    #pragma unroll
    for (int b = 0; b < 2; b++)
        #pragma unroll
        for (int c = 0; c < 4; c++) master[b][c] = 0.f;

    #pragma unroll
    for (int s = 0; s < FR_STAGES - 1; s++) { load_stage(s, s * 32); CP_COMMIT(); }

    // B-operand ldsm4 lane mapping: mat = lane>>3 -> (ni = mat>>1, kh = mat&1)
    const int b_ni = (lane >> 4) & 1;       // mat>>1
    const int b_kh = (lane >> 3) & 1;       // mat&1
    const int b_row = wn * 16 + b_ni * 8 + (lane & 7);

    constexpr int NS = H_ / 32;     // 64 stages, BK=32
    for (int s = 0; s < NS; s++) {
        int buf = s % FR_STAGES;
        CP_WAIT4();
        __syncthreads();
        if (s + FR_STAGES - 1 < NS)
            load_stage((s + FR_STAGES - 1) % FR_STAGES, (s + FR_STAGES - 1) * 32);
        CP_COMMIT();

        float tacc[2][4];
        #pragma unroll
        for (int b = 0; b < 2; b++)
            #pragma unroll
            for (int c = 0; c < 4; c++) tacc[b][c] = 0.f;

        uint32_t sb = smem_u32(smf + (size_t)buf * ST_EL);
        #pragma unroll
        for (int kk = 0; kk < 2; kk++) {
            uint32_t af[4];
            {
                int row = wm * 16 + l15;
                ldsm4(af, sb + (uint32_t)((row * SPD + (lane >> 4) * 8) * 2 + kk * 32));
            }
            #pragma unroll
            for (int p = 0; p < 3; p++) {
                uint32_t ab = sb + (uint32_t)((ST_SPK + p * ST_A) * 2);
                uint32_t r4[4];
                ldsm4(r4, ab + (uint32_t)((b_row * SPD + kk * 16 + b_kh * 8) * 2));
                mma16816(tacc[0], af, r4);       // ni=0 frag {r0,r1}
                mma16816(tacc[1], af, r4 + 2);   // ni=1 frag {r2,r3}
            }
        }
        #pragma unroll
        for (int b = 0; b < 2; b++)
            #pragma unroll
            for (int c = 0; c < 4; c++) master[b][c] += tacc[b][c];
    }

    // fused epilogue — identical arithmetic, streaming hints
    __nv_bfloat16* Sout = gS[t & 1];
    const int gq = lane >> 2, tq = lane & 3;
    #pragma unroll
    for (int ni = 0; ni < 2; ni++)
        #pragma unroll
        for (int h = 0; h < 2; h++)
            #pragma unroll
            for (int e = 0; e < 2; e++) {
                int b = m0 + wm * 16 + gq + h * 8;
                int n = n0 + wn * 16 + ni * 8 + tq * 2 + e;
                size_t o = ((size_t)b * T_ + t) * H_ + n;
                float u = __ldcs(&g_U[o]);
                float sp_prev  = __ldcs(&out_spikes[o - H_]);
                float mem_prev = __ldcs(&out_mems[o - H_]);
                float y = tanhf(0.5f * master[ni][h * 2 + e] + u);
                float mem = mem_prev * 0.5f - 0.5f * (1.0f - sp_prev) + y;
                float sp = (mem > 0.5f) ? 1.0f : 0.0f;
                __stcs(&out_mems[o], mem);
                __stcs(&out_spikes[o], sp);
                Sout[(size_t)b * H_ + n] = __float2bfloat16(sp);
            }
}

// ----------------------------------------------------------------------------
extern "C" void kernel_launch(void* const* d_in, const int* in_sizes, int n_in,
                              void* d_out, int out_size)
{
    const float* x        = (const float*)d_in[0];
    const float* W_in     = (const float*)d_in[1];
    const float* Arec     = (const float*)d_in[2];
    const float* bias     = (const float*)d_in[3];
    const float* mem_init = (const float*)d_in[4];

    float* out        = (float*)d_out;
    float* out_mems   = out;
    float* out_spikes = out + (size_t)B_ * T_ * H_;

    cudaFuncSetAttribute(k_frame_mma,
                         cudaFuncAttributeMaxDynamicSharedMemorySize, FR_SMEM_B);

    { dim3 g(H_ / 32, H_ / 32), b(32, 8); k_split_A<<<g, b>>>(Arec); }
    { dim3 g(H_ / 128, (B_ * T_) / 128); k_input_gemm<<<g, 256>>>(x, W_in, bias); }

    k_frame0<<<(B_ * H_) / 256, 256>>>(mem_init, out_mems, out_spikes);

    dim3 g(H_ / 32, B_ / 64);
    for (int t = 1; t < T_; t++)
        k_frame_mma<<<g, 256, FR_SMEM_B>>>(out_mems, out_spikes, t);
}

// round 10
// speedup vs baseline: 1.0545x; 1.0545x over previous
#include <cuda_runtime.h>
#include <cuda_bf16.h>
#include <math.h>
#include <stdint.h>

#define B_    256
#define T_    128
#define NIN   700
#define H_    2048

// ---------------- device scratch ----------------
// g_U is T-MAJOR: [t][b][n]  (row r = t*B_ + b)
__device__ float         g_U [(size_t)B_ * T_ * H_];
__device__ __nv_bfloat16 gA0 [(size_t)H_ * H_];         // A^T splits [n][k]
__device__ __nv_bfloat16 gA1 [(size_t)H_ * H_];
__device__ __nv_bfloat16 gA2 [(size_t)H_ * H_];
__device__ __nv_bfloat16 gS  [2][(size_t)B_ * H_];      // spike ping-pong (exact 0/1)

// ---------------- asm helpers (sm_80+ portable) ----------------
__device__ __forceinline__ uint32_t smem_u32(const void* p) {
    uint32_t a;
    asm("{ .reg .u64 t; cvta.to.shared.u64 t, %1; cvt.u32.u64 %0, t; }"
        : "=r"(a) : "l"(p));
    return a;
}
__device__ __forceinline__ void cpa16(uint32_t dst, const void* src) {
    asm volatile("cp.async.cg.shared.global [%0], [%1], 16;"
                 :: "r"(dst), "l"(src) : "memory");
}
// zfill variant: src_size 0 -> 16 bytes of zeros (exact +0 contributions)
__device__ __forceinline__ void cpa16_z(uint32_t dst, const void* src, bool v) {
    uint32_t sz = v ? 16u : 0u;
    asm volatile("cp.async.cg.shared.global [%0], [%1], 16, %2;"
                 :: "r"(dst), "l"(src), "r"(sz) : "memory");
}
#define CP_COMMIT() asm volatile("cp.async.commit_group;" ::: "memory")
#define CP_WAIT0()  asm volatile("cp.async.wait_group 0;" ::: "memory")
#define CP_WAIT1()  asm volatile("cp.async.wait_group 1;" ::: "memory")

__device__ __forceinline__ void ldsm4(uint32_t* r, uint32_t a) {
    asm volatile("ldmatrix.sync.aligned.m8n8.x4.shared.b16 {%0,%1,%2,%3}, [%4];"
                 : "=r"(r[0]), "=r"(r[1]), "=r"(r[2]), "=r"(r[3]) : "r"(a));
}
__device__ __forceinline__ void ldsm2(uint32_t* r, uint32_t a) {
    asm volatile("ldmatrix.sync.aligned.m8n8.x2.shared.b16 {%0,%1}, [%2];"
                 : "=r"(r[0]), "=r"(r[1]) : "r"(a));
}
__device__ __forceinline__ void mma16816(float* c, const uint32_t* a,
                                         const uint32_t* b) {
    asm volatile("mma.sync.aligned.m16n8k16.row.col.f32.bf16.bf16.f32 "
                 "{%0,%1,%2,%3}, {%4,%5,%6,%7}, {%8,%9}, {%0,%1,%2,%3};"
                 : "+f"(c[0]), "+f"(c[1]), "+f"(c[2]), "+f"(c[3])
                 : "r"(a[0]), "r"(a[1]), "r"(a[2]), "r"(a[3]),
                   "r"(b[0]), "r"(b[1]));
}

// ---------------- bf16 3-way exact split ----------------
__device__ __forceinline__ void split3(float v, __nv_bfloat16& b0,
                                       __nv_bfloat16& b1, __nv_bfloat16& b2) {
    b0 = __float2bfloat16(v);
    float f0 = __bfloat162float(b0);
    b1 = __float2bfloat16(v - f0);
    float f1 = __bfloat162float(b1);
    b2 = __float2bfloat16(v - f0 - f1);
}

// ---------------- device body: A-split CTA (transpose + split) -------------
__device__ void split_cta_body(int sb, const float* __restrict__ A, char* smraw)
{
    float (*tile)[33] = (float(*)[33])smraw;
    const int tid = threadIdx.x;
    const int tx = tid & 31, ty = tid >> 5;        // (32, 8)
    const int gx = sb & 63, gy = sb >> 6;
    const int kbase = gy * 32, nbase = gx * 32;
    #pragma unroll
    for (int i = 0; i < 32; i += 8)
        tile[ty + i][tx] = A[(size_t)(kbase + ty + i) * H_ + nbase + tx];
    __syncthreads();
    #pragma unroll
    for (int i = 0; i < 32; i += 8) {
        float v = tile[tx][ty + i];
        size_t o = (size_t)(nbase + ty + i) * H_ + kbase + tx;
        __nv_bfloat16 b0, b1, b2; split3(v, b0, b1, b2);
        gA0[o] = b0; gA1[o] = b1; gA2[o] = b2;
    }
}

// ---------------- device body: one input-GEMM tile (fp32, BK=16) -----------
// Writes g_U rows [mt*128, mt*128+128) (t-major), cols [nt*128, nt*128+128).
// Per-element FP order identical to the proven round-9 kernel (ascending k,
// zfill-zero tail = exact +0 terms).
__device__ void gemm_tile_body(int mt, int nt,
                               const float* __restrict__ X,
                               const float* __restrict__ W,
                               const float* __restrict__ bias, char* smraw)
{
    constexpr int BK = 16, TM = 8, TN = 8;
    float (*As)[128][BK] = (float(*)[128][BK])smraw;            // 2 x 8KB
    float (*Bs)[BK][128] = (float(*)[BK][128])(smraw + 16384);  // 2 x 8KB

    const int tid = threadIdx.x;
    const int tRow = (tid >> 4) << 3, tCol = (tid & 15) << 3;
    const int m0g = mt * 128, n0g = nt * 128;

    auto xrow = [&](int r) -> const float* {
        int rr = m0g + r;                 // t-major row
        int b = rr & (B_ - 1), t = rr >> 8;
        return X + ((size_t)b * T_ + t) * NIN;
    };
    auto load_stage = [&](int buf, int k0) {
        #pragma unroll
        for (int h = 0; h < 2; h++) {
            int c = tid + h * 256;
            int ar = c >> 2, aj = (c & 3) * 4;
            cpa16_z(smem_u32(&As[buf][ar][aj]), xrow(ar) + k0 + aj,
                    (k0 + aj) < NIN);
            int brw = c >> 5, bc = (c & 31) * 4;
            cpa16_z(smem_u32(&Bs[buf][brw][bc]),
                    W + (size_t)(k0 + brw) * H_ + n0g + bc, (k0 + brw) < NIN);
        }
    };

    float acc[TM][TN];
    #pragma unroll
    for (int i = 0; i < TM; i++)
        #pragma unroll
        for (int j = 0; j < TN; j++) acc[i][j] = 0.f;

    constexpr int NS = (NIN + BK - 1) / BK;   // 44
    load_stage(0, 0); CP_COMMIT();

    for (int s = 0; s < NS; s++) {
        int buf = s & 1;
        __syncthreads();
        if (s + 1 < NS) { load_stage(buf ^ 1, (s + 1) * BK); CP_COMMIT(); CP_WAIT1(); }
        else CP_WAIT0();
        __syncthreads();

        #pragma unroll
        for (int k = 0; k < BK; k++) {
            float aF[TM], bF[TN];
            #pragma unroll
            for (int i = 0; i < TM; i++) aF[i] = As[buf][tRow + i][k];
            float4 b0 = *(const float4*)&Bs[buf][k][tCol];
            float4 b1 = *(const float4*)&Bs[buf][k][tCol + 4];
            bF[0] = b0.x; bF[1] = b0.y; bF[2] = b0.z; bF[3] = b0.w;
            bF[4] = b1.x; bF[5] = b1.y; bF[6] = b1.z; bF[7] = b1.w;
            #pragma unroll
            for (int i = 0; i < TM; i++)
                #pragma unroll
                for (int j = 0; j < TN; j++) acc[i][j] += aF[i] * bF[j];
        }
    }

    const int n0 = n0g + tCol;
    #pragma unroll
    for (int i = 0; i < TM; i++) {
        size_t row = (size_t)(m0g + tRow + i) * H_;
        #pragma unroll
        for (int j = 0; j < TN; j++)
            __stcs(&g_U[row + n0 + j], 0.5f * (acc[i][j] + bias[n0 + j]));
    }
}

// ---------------- device body: one recurrent-frame tile (round-6 verbatim) -
#define SPD 40                          // padded row stride (bf16 elems)
#define FTILE (64 * SPD)                // 2560 elems / 5120 B per tile
#define FR_SMEM_B (2 * 4 * FTILE * 2)   // 40960 B

__device__ void frame_body(int fb, float* __restrict__ out_mems,
                           float* __restrict__ out_spikes, int t, char* smraw)
{
    __nv_bfloat16* smf = (__nv_bfloat16*)smraw;      // [2][4][FTILE]
    const int tid = threadIdx.x;
    const int lane = tid & 31, w = tid >> 5;
    const int wm = w & 1, wn = w >> 1;               // warp tile 32(m) x 16(n)
    const int l15 = lane & 15;
    const int n0 = (fb & 31) * 64, m0 = (fb >> 5) * 64;

    const __nv_bfloat16* Sg = gS[(t + 1) & 1];
    const __nv_bfloat16* Ap[3] = { gA0 + (size_t)n0 * H_,
                                   gA1 + (size_t)n0 * H_,
                                   gA2 + (size_t)n0 * H_ };

    auto tilep = [&](int buf, int tl) {
        return smf + ((size_t)buf * 4 + tl) * FTILE;
    };
    const int lr = tid >> 2, lj = (tid & 3) * 8;
    auto load_stage = [&](int buf, int k0) {
        cpa16(smem_u32(tilep(buf, 0) + lr * SPD + lj),
              Sg + (size_t)(m0 + lr) * H_ + k0 + lj);
        #pragma unroll
        for (int p = 0; p < 3; p++)
            cpa16(smem_u32(tilep(buf, 1 + p) + lr * SPD + lj),
                  Ap[p] + (size_t)lr * H_ + k0 + lj);
    };

    float master[2][2][4];
    #pragma unroll
    for (int a = 0; a < 2; a++)
        #pragma unroll
        for (int b = 0; b < 2; b++)
            #pragma unroll
            for (int c = 0; c < 4; c++) master[a][b][c] = 0.f;

    load_stage(0, 0); CP_COMMIT();

    constexpr int NS = H_ / 32;     // 64 stages, BK=32
    for (int s = 0; s < NS; s++) {
        int buf = s & 1;
        if (s + 1 < NS) { load_stage(buf ^ 1, (s + 1) * 32); CP_COMMIT(); CP_WAIT1(); }
        else CP_WAIT0();
        __syncthreads();

        float tacc[2][2][4];
        #pragma unroll
        for (int a = 0; a < 2; a++)
            #pragma unroll
            for (int b = 0; b < 2; b++)
                #pragma unroll
                for (int c = 0; c < 4; c++) tacc[a][b][c] = 0.f;

        uint32_t sb = smem_u32(tilep(buf, 0));
        #pragma unroll
        for (int kk = 0; kk < 2; kk++) {
            uint32_t af[2][4];
            #pragma unroll
            for (int mi = 0; mi < 2; mi++) {
                int row = wm * 32 + mi * 16 + l15;
                ldsm4(af[mi], sb + (uint32_t)((row * SPD + (lane >> 4) * 8) * 2 + kk * 32));
            }
            #pragma unroll
            for (int p = 0; p < 3; p++) {
                uint32_t ab = smem_u32(tilep(buf, 1 + p));
                #pragma unroll
                for (int ni = 0; ni < 2; ni++) {
                    uint32_t bfr[2];
                    int row = wn * 16 + ni * 8 + (l15 & 7);
                    ldsm2(bfr, ab + (uint32_t)((row * SPD + ((l15 >> 3) & 1) * 8) * 2 + kk * 32));
                    mma16816(tacc[0][ni], af[0], bfr);
                    mma16816(tacc[1][ni], af[1], bfr);
                }
            }
        }
        #pragma unroll
        for (int a = 0; a < 2; a++)
            #pragma unroll
            for (int b = 0; b < 2; b++)
                #pragma unroll
                for (int c = 0; c < 4; c++) master[a][b][c] += tacc[a][b][c];

        __syncthreads();
    }

    // fused epilogue — arithmetic identical to the passing round-6 kernel
    __nv_bfloat16* Sout = gS[t & 1];
    const int gq = lane >> 2, tq = lane & 3;
    #pragma unroll
    for (int mi = 0; mi < 2; mi++)
        #pragma unroll
        for (int ni = 0; ni < 2; ni++)
            #pragma unroll
            for (int h = 0; h < 2; h++)
                #pragma unroll
                for (int e = 0; e < 2; e++) {
                    int b = m0 + wm * 32 + mi * 16 + gq + h * 8;
                    int n = n0 + wn * 16 + ni * 8 + tq * 2 + e;
                    size_t o = ((size_t)b * T_ + t) * H_ + n;
                    float u = __ldcs(&g_U[((size_t)t * B_ + b) * H_ + n]);
                    float sp_prev  = __ldcs(&out_spikes[o - H_]);
                    float mem_prev = __ldcs(&out_mems[o - H_]);
                    float y = tanhf(0.5f * master[mi][ni][h * 2 + e] + u);
                    float mem = mem_prev * 0.5f - 0.5f * (1.0f - sp_prev) + y;
                    float sp = (mem > 0.5f) ? 1.0f : 0.0f;
                    __stcs(&out_mems[o], mem);
                    __stcs(&out_spikes[o], sp);
                    Sout[(size_t)b * H_ + n] = __float2bfloat16(sp);
                }
}

// ---------------- kernels ----------------
// Pre: GEMM tiles 0..63 (g_U for t in [0,2)) + all 4096 A-split CTAs.
__global__ void __launch_bounds__(256)
k_pre(const float* __restrict__ X, const float* __restrict__ W,
      const float* __restrict__ A, const float* __restrict__ bias)
{
    __shared__ __align__(16) char smraw[FR_SMEM_B];
    int bx = blockIdx.x;
    if (bx < 64) gemm_tile_body(bx >> 4, bx & 15, X, W, bias, smraw);
    else         split_cta_body(bx - 64, A, smraw);
}

// Frame 0 (spike0 = 0 -> r = 0): elementwise
__global__ void k_frame0(const float* __restrict__ mem_init,
                         float* __restrict__ out_mems,
                         float* __restrict__ out_spikes)
{
    size_t idx = (size_t)blockIdx.x * 256 + threadIdx.x;
    int b = (int)(idx / H_), n = (int)(idx % H_);
    size_t o = ((size_t)b * T_) * H_ + n;
    float u = g_U[(size_t)b * H_ + n];          // t=0 slice, t-major
    float y = tanhf(u);
    float mem = mem_init[idx] * 0.5f - 0.5f * (1.0f - 0.0f) + y;
    float sp = (mem > 0.5f) ? 1.0f : 0.0f;
    out_mems[o] = mem;
    out_spikes[o] = sp;
    gS[0][idx] = __float2bfloat16(sp);
}

// Fused frame launch: CTAs 0..127 = frame tiles for frame t;
// CTAs 128..255 (t <= 32 only) = input-GEMM tiles for future frames.
__global__ void __launch_bounds__(256)
k_fused(const float* __restrict__ X, const float* __restrict__ W,
        const float* __restrict__ bias,
        float* __restrict__ out_mems, float* __restrict__ out_spikes, int t)
{
    __shared__ __align__(16) char smraw[FR_SMEM_B];
    int bx = blockIdx.x;
    if (bx < 128) {
        frame_body(bx, out_mems, out_spikes, t, smraw);
    } else {
        int tile = 64 + (t - 1) * 128 + (bx - 128);
        if (tile < 4096)
            gemm_tile_body(tile >> 4, tile & 15, X, W, bias, smraw);
    }
}

// ----------------------------------------------------------------------------
extern "C" void kernel_launch(void* const* d_in, const int* in_sizes, int n_in,
                              void* d_out, int out_size)
{
    const float* x        = (const float*)d_in[0];
    const float* W_in     = (const float*)d_in[1];
    const float* Arec     = (const float*)d_in[2];
    const float* bias     = (const float*)d_in[3];
    const float* mem_init = (const float*)d_in[4];

    float* out        = (float*)d_out;
    float* out_mems   = out;
    float* out_spikes = out + (size_t)B_ * T_ * H_;

    // 1) Pre: g_U tiles for t in [0,2) + A splits (independent CTAs).
    k_pre<<<64 + 4096, 256>>>(x, W_in, Arec, bias);

    // 2) Frame 0 (needs g_U t=0 only).
    k_frame0<<<(B_ * H_) / 256, 256>>>(mem_init, out_mems, out_spikes);

    // 3) Frames 1..127; launches 1..32 also carry 128 input-GEMM tiles each
    //    (tile coverage always >= 1 frame ahead of the reader).
    for (int t = 1; t < T_; t++) {
        int grid = (t <= 32) ? 256 : 128;
        k_fused<<<grid, 256>>>(x, W_in, bias, out_mems, out_spikes, t);
    }
}

// round 11
// speedup vs baseline: 1.2059x; 1.1436x over previous
#include <cuda_runtime.h>
#include <cuda_bf16.h>
#include <math.h>
#include <stdint.h>

#define B_    256
#define T_    128
#define NIN   700
#define H_    2048

// ---------------- device scratch ----------------
__device__ float         g_U [(size_t)B_ * T_ * H_];    // 0.5*(x@W+bias), b-major
__device__ __nv_bfloat16 gA0 [(size_t)H_ * H_];         // A^T splits [n][k]
__device__ __nv_bfloat16 gA1 [(size_t)H_ * H_];
__device__ __nv_bfloat16 gA2 [(size_t)H_ * H_];
__device__ __nv_bfloat16 gS  [2][(size_t)B_ * H_];      // spike ping-pong (exact 0/1)

// ---------------- asm helpers (sm_80+ portable) ----------------
__device__ __forceinline__ uint32_t smem_u32(const void* p) {
    uint32_t a;
    asm("{ .reg .u64 t; cvta.to.shared.u64 t, %1; cvt.u32.u64 %0, t; }"
        : "=r"(a) : "l"(p));
    return a;
}
__device__ __forceinline__ void cpa16(uint32_t dst, const void* src) {
    asm volatile("cp.async.cg.shared.global [%0], [%1], 16;"
                 :: "r"(dst), "l"(src) : "memory");
}
// zfill variant: src_size 0 -> 16 bytes of zeros (exact +0 contributions)
__device__ __forceinline__ void cpa16_z(uint32_t dst, const void* src, bool v) {
    uint32_t sz = v ? 16u : 0u;
    asm volatile("cp.async.cg.shared.global [%0], [%1], 16, %2;"
                 :: "r"(dst), "l"(src), "r"(sz) : "memory");
}
#define CP_COMMIT() asm volatile("cp.async.commit_group;" ::: "memory")
#define CP_WAIT0()  asm volatile("cp.async.wait_group 0;" ::: "memory")
#define CP_WAIT1()  asm volatile("cp.async.wait_group 1;" ::: "memory")

__device__ __forceinline__ void ldsm4(uint32_t* r, uint32_t a) {
    asm volatile("ldmatrix.sync.aligned.m8n8.x4.shared.b16 {%0,%1,%2,%3}, [%4];"
                 : "=r"(r[0]), "=r"(r[1]), "=r"(r[2]), "=r"(r[3]) : "r"(a));
}
__device__ __forceinline__ void ldsm2(uint32_t* r, uint32_t a) {
    asm volatile("ldmatrix.sync.aligned.m8n8.x2.shared.b16 {%0,%1}, [%2];"
                 : "=r"(r[0]), "=r"(r[1]) : "r"(a));
}
__device__ __forceinline__ void mma16816(float* c, const uint32_t* a,
                                         const uint32_t* b) {
    asm volatile("mma.sync.aligned.m16n8k16.row.col.f32.bf16.bf16.f32 "
                 "{%0,%1,%2,%3}, {%4,%5,%6,%7}, {%8,%9}, {%0,%1,%2,%3};"
                 : "+f"(c[0]), "+f"(c[1]), "+f"(c[2]), "+f"(c[3])
                 : "r"(a[0]), "r"(a[1]), "r"(a[2]), "r"(a[3]),
                   "r"(b[0]), "r"(b[1]));
}

// ---------------- bf16 3-way exact split ----------------
__device__ __forceinline__ void split3(float v, __nv_bfloat16& b0,
                                       __nv_bfloat16& b1, __nv_bfloat16& b2) {
    b0 = __float2bfloat16(v);
    float f0 = __bfloat162float(b0);
    b1 = __float2bfloat16(v - f0);
    float f1 = __bfloat162float(b1);
    b2 = __float2bfloat16(v - f0 - f1);
}

__global__ void k_split_A(const float* __restrict__ A) {
    __shared__ float tile[32][33];
    int tx = threadIdx.x, ty = threadIdx.y;
    int kbase = blockIdx.y * 32, nbase = blockIdx.x * 32;
    #pragma unroll
    for (int i = 0; i < 32; i += 8)
        tile[ty + i][tx] = A[(size_t)(kbase + ty + i) * H_ + nbase + tx];
    __syncthreads();
    #pragma unroll
    for (int i = 0; i < 32; i += 8) {
        float v = tile[tx][ty + i];
        size_t o = (size_t)(nbase + ty + i) * H_ + kbase + tx;
        __nv_bfloat16 b0, b1, b2; split3(v, b0, b1, b2);
        gA0[o] = b0; gA1[o] = b1; gA2[o] = b2;
    }
}

// ------- input GEMM: fp32, ascending-k FFMA (bit-identical, round-9) -------
__global__ void __launch_bounds__(256) k_input_gemm(
    const float* __restrict__ X, const float* __restrict__ W,
    const float* __restrict__ bias)
{
    constexpr int K = NIN, N = H_;
    constexpr int BM = 128, BN = 128, BK = 16, TM = 8, TN = 8;
    __shared__ __align__(16) float As[2][BM][BK];
    __shared__ __align__(16) float Bs[2][BK][BN];

    const int tid = threadIdx.x;
    const int bm = blockIdx.y, bn = blockIdx.x;
    const int tRow = (tid >> 4) << 3, tCol = (tid & 15) << 3;
    const int m0g = bm * BM, n0g = bn * BN;

    auto load_stage = [&](int buf, int k0) {
        #pragma unroll
        for (int h = 0; h < 2; h++) {
            int c = tid + h * 256;
            int ar = c >> 2, aj = (c & 3) * 4;
            cpa16_z(smem_u32(&As[buf][ar][aj]),
                    X + (size_t)(m0g + ar) * K + k0 + aj, (k0 + aj) < K);
            int brw = c >> 5, bc = (c & 31) * 4;
            cpa16_z(smem_u32(&Bs[buf][brw][bc]),
                    W + (size_t)(k0 + brw) * N + n0g + bc, (k0 + brw) < K);
        }
    };

    float acc[TM][TN];
    #pragma unroll
    for (int i = 0; i < TM; i++)
        #pragma unroll
        for (int j = 0; j < TN; j++) acc[i][j] = 0.f;

    constexpr int NS = (K + BK - 1) / BK;   // 44
    load_stage(0, 0); CP_COMMIT();

    for (int s = 0; s < NS; s++) {
        int buf = s & 1;
        __syncthreads();
        if (s + 1 < NS) { load_stage(buf ^ 1, (s + 1) * BK); CP_COMMIT(); CP_WAIT1(); }
        else CP_WAIT0();
        __syncthreads();

        #pragma unroll
        for (int k = 0; k < BK; k++) {
            float aF[TM], bF[TN];
            #pragma unroll
            for (int i = 0; i < TM; i++) aF[i] = As[buf][tRow + i][k];
            float4 b0 = *(const float4*)&Bs[buf][k][tCol];
            float4 b1 = *(const float4*)&Bs[buf][k][tCol + 4];
            bF[0] = b0.x; bF[1] = b0.y; bF[2] = b0.z; bF[3] = b0.w;
            bF[4] = b1.x; bF[5] = b1.y; bF[6] = b1.z; bF[7] = b1.w;
            #pragma unroll
            for (int i = 0; i < TM; i++)
                #pragma unroll
                for (int j = 0; j < TN; j++) acc[i][j] += aF[i] * bF[j];
        }
    }

    const int m0 = m0g + tRow, n0 = n0g + tCol;
    #pragma unroll
    for (int i = 0; i < TM; i++) {
        size_t row = (size_t)(m0 + i) * N;
        #pragma unroll
        for (int j = 0; j < TN; j++)
            g_U[row + n0 + j] = 0.5f * (acc[i][j] + bias[n0 + j]);
    }
}

// ---------------- frame 0 (spike0 = 0 -> r = 0) ----------------
__global__ void k_frame0(const float* __restrict__ mem_init,
                         float* __restrict__ out_mems,
                         float* __restrict__ out_spikes)
{
    size_t idx = (size_t)blockIdx.x * 256 + threadIdx.x;
    int b = (int)(idx / H_), n = (int)(idx % H_);
    size_t o = ((size_t)b * T_) * H_ + n;
    float u = g_U[o];
    float y = tanhf(u);
    float mem = mem_init[idx] * 0.5f - 0.5f * (1.0f - 0.0f) + y;
    float sp = (mem > 0.5f) ? 1.0f : 0.0f;
    out_mems[o] = mem;
    out_spikes[o] = sp;
    gS[0][idx] = __float2bfloat16(sp);
}

// ==== recurrent frame v2: BK=64 stages, 3-buffer ring, 1 barrier/stage =====
// Per-element accumulation order BIT-IDENTICAL to rounds 6/8/9/10: per BK=32
// chunk (two per stage): tacc=0; chain kk0p0,kk0p1,kk0p2,kk1p0,kk1p1,kk1p2;
// master += tacc (IEEE fp32).
#define SPD2 72                          // padded row stride (bf16 elems)
#define TSZ  (64 * SPD2)                 // 4608 elems per 64x64 tile
#define STG  (4 * TSZ)                   // spike + 3 A tiles = 18432 elems
#define FR_SMEM_B (3 * STG * 2)          // 110592 B

__global__ void __launch_bounds__(256)
k_frame_mma(float* __restrict__ out_mems, float* __restrict__ out_spikes, int t)
{
    extern __shared__ __align__(16) __nv_bfloat16 smf[];
    const int tid = threadIdx.x;
    const int lane = tid & 31, w = tid >> 5;
    const int wm = w & 1, wn = w >> 1;               // warp tile 32(m) x 16(n)
    const int l15 = lane & 15;
    const int n0 = blockIdx.x * 64, m0 = blockIdx.y * 64;

    const __nv_bfloat16* Sg = gS[(t + 1) & 1];
    const __nv_bfloat16* Ap[3] = { gA0 + (size_t)n0 * H_,
                                   gA1 + (size_t)n0 * H_,
                                   gA2 + (size_t)n0 * H_ };

    // stage = 4 tiles x 64 rows x 64 elems = 2048 x 16B chunks, 8 per thread
    auto load_stage = [&](int buf, int k0) {
        __nv_bfloat16* st = smf + (size_t)buf * STG;
        #pragma unroll
        for (int i = 0; i < 8; i++) {
            int c = tid + i * 256;
            int tile = c >> 9;                    // 0..3
            int r = (c >> 3) & 63;
            int j = (c & 7) * 8;
            const __nv_bfloat16* src = (tile == 0)
                ? Sg + (size_t)(m0 + r) * H_ + k0 + j
                : Ap[tile - 1] + (size_t)r * H_ + k0 + j;
            cpa16(smem_u32(st + tile * TSZ + r * SPD2 + j), src);
        }
    };

    float master[2][2][4];
    #pragma unroll
    for (int a = 0; a < 2; a++)
        #pragma unroll
        for (int b = 0; b < 2; b++)
            #pragma unroll
            for (int c = 0; c < 4; c++) master[a][b][c] = 0.f;

    load_stage(0, 0);  CP_COMMIT();
    load_stage(1, 64); CP_COMMIT();

    const int a_row = wm * 32 + l15;          // + mi*16 below
    const int b_rb  = wn * 16 + (l15 & 7);    // + ni*8 below
    const int a_co  = (lane >> 4) * 8;        // 16B half select (elems)
    const int b_co  = ((l15 >> 3) & 1) * 8;

    constexpr int NS = H_ / 64;     // 32 stages, BK=64 (2 x BK=32 chunks)
    for (int s = 0; s < NS; s++) {
        int buf = s % 3;
        CP_WAIT1();
        __syncthreads();
        if (s + 2 < NS) load_stage((s + 2) % 3, (s + 2) * 64);
        CP_COMMIT();

        uint32_t sb = smem_u32(smf + (size_t)buf * STG);
        #pragma unroll
        for (int c32 = 0; c32 < 2; c32++) {
            const uint32_t kbyte = (uint32_t)c32 * 64;   // 32 elems * 2B

            float tacc[2][2][4];
            #pragma unroll
            for (int a = 0; a < 2; a++)
                #pragma unroll
                for (int b = 0; b < 2; b++)
                    #pragma unroll
                    for (int c = 0; c < 4; c++) tacc[a][b][c] = 0.f;

            #pragma unroll
            for (int kk = 0; kk < 2; kk++) {
                uint32_t af[2][4];
                #pragma unroll
                for (int mi = 0; mi < 2; mi++) {
                    int row = a_row + mi * 16;
                    ldsm4(af[mi], sb + (uint32_t)((row * SPD2 + a_co) * 2
                                                  + kbyte + kk * 32));
                }
                #pragma unroll
                for (int p = 0; p < 3; p++) {
                    uint32_t ab = sb + (uint32_t)((1 + p) * TSZ * 2);
                    #pragma unroll
                    for (int ni = 0; ni < 2; ni++) {
                        uint32_t bfr[2];
                        int row = b_rb + ni * 8;
                        ldsm2(bfr, ab + (uint32_t)((row * SPD2 + b_co) * 2
                                                   + kbyte + kk * 32));
                        mma16816(tacc[0][ni], af[0], bfr);
                        mma16816(tacc[1][ni], af[1], bfr);
                    }
                }
            }
            #pragma unroll
            for (int a = 0; a < 2; a++)
                #pragma unroll
                for (int b = 0; b < 2; b++)
                    #pragma unroll
                    for (int c = 0; c < 4; c++) master[a][b][c] += tacc[a][b][c];
        }
    }

    // fused epilogue — arithmetic identical to rounds 6/9
    __nv_bfloat16* Sout = gS[t & 1];
    const int gq = lane >> 2, tq = lane & 3;
    #pragma unroll
    for (int mi = 0; mi < 2; mi++)
        #pragma unroll
        for (int ni = 0; ni < 2; ni++)
            #pragma unroll
            for (int h = 0; h < 2; h++)
                #pragma unroll
                for (int e = 0; e < 2; e++) {
                    int b = m0 + wm * 32 + mi * 16 + gq + h * 8;
                    int n = n0 + wn * 16 + ni * 8 + tq * 2 + e;
                    size_t o = ((size_t)b * T_ + t) * H_ + n;
                    float u = __ldcs(&g_U[o]);
                    float sp_prev  = __ldcs(&out_spikes[o - H_]);
                    float mem_prev = __ldcs(&out_mems[o - H_]);
                    float y = tanhf(0.5f * master[mi][ni][h * 2 + e] + u);
                    float mem = mem_prev * 0.5f - 0.5f * (1.0f - sp_prev) + y;
                    float sp = (mem > 0.5f) ? 1.0f : 0.0f;
                    __stcs(&out_mems[o], mem);
                    __stcs(&out_spikes[o], sp);
                    Sout[(size_t)b * H_ + n] = __float2bfloat16(sp);
                }
}

// ----------------------------------------------------------------------------
extern "C" void kernel_launch(void* const* d_in, const int* in_sizes, int n_in,
                              void* d_out, int out_size)
{
    const float* x        = (const float*)d_in[0];
    const float* W_in     = (const float*)d_in[1];
    const float* Arec     = (const float*)d_in[2];
    const float* bias     = (const float*)d_in[3];
    const float* mem_init = (const float*)d_in[4];

    float* out        = (float*)d_out;
    float* out_mems   = out;
    float* out_spikes = out + (size_t)B_ * T_ * H_;

    cudaFuncSetAttribute(k_frame_mma,
                         cudaFuncAttributeMaxDynamicSharedMemorySize, FR_SMEM_B);

    { dim3 g(H_ / 32, H_ / 32), b(32, 8); k_split_A<<<g, b>>>(Arec); }
    { dim3 g(H_ / 128, (B_ * T_) / 128); k_input_gemm<<<g, 256>>>(x, W_in, bias); }

    k_frame0<<<(B_ * H_) / 256, 256>>>(mem_init, out_mems, out_spikes);

    dim3 g(H_ / 64, B_ / 64);
    for (int t = 1; t < T_; t++)
        k_frame_mma<<<g, 256, FR_SMEM_B>>>(out_mems, out_spikes, t);
}

// round 12
// speedup vs baseline: 1.2488x; 1.0355x over previous
#include <cuda_runtime.h>
#include <cuda_bf16.h>
#include <math.h>
#include <stdint.h>

#define B_    256
#define T_    128
#define NIN   700
#define H_    2048

// ---------------- device scratch ----------------
__device__ float         g_U [(size_t)B_ * T_ * H_];    // 0.5*(x@W+bias), b-major
__device__ __nv_bfloat16 gA0 [(size_t)H_ * H_];         // A^T splits [n][k]
__device__ __nv_bfloat16 gA1 [(size_t)H_ * H_];
__device__ __nv_bfloat16 gA2 [(size_t)H_ * H_];
__device__ __nv_bfloat16 gS  [2][(size_t)B_ * H_];      // spike ping-pong (exact 0/1)
__device__ unsigned      gCnt[T_][4];                   // group barrier counters

// ---------------- asm helpers (sm_80+ portable) ----------------
__device__ __forceinline__ uint32_t smem_u32(const void* p) {
    uint32_t a;
    asm("{ .reg .u64 t; cvta.to.shared.u64 t, %1; cvt.u32.u64 %0, t; }"
        : "=r"(a) : "l"(p));
    return a;
}
__device__ __forceinline__ void cpa16(uint32_t dst, const void* src) {
    asm volatile("cp.async.cg.shared.global [%0], [%1], 16;"
                 :: "r"(dst), "l"(src) : "memory");
}
__device__ __forceinline__ void cpa16_z(uint32_t dst, const void* src, bool v) {
    uint32_t sz = v ? 16u : 0u;
    asm volatile("cp.async.cg.shared.global [%0], [%1], 16, %2;"
                 :: "r"(dst), "l"(src), "r"(sz) : "memory");
}
#define CP_COMMIT() asm volatile("cp.async.commit_group;" ::: "memory")
#define CP_WAIT0()  asm volatile("cp.async.wait_group 0;" ::: "memory")
#define CP_WAIT1()  asm volatile("cp.async.wait_group 1;" ::: "memory")

__device__ __forceinline__ void ldsm4(uint32_t* r, uint32_t a) {
    asm volatile("ldmatrix.sync.aligned.m8n8.x4.shared.b16 {%0,%1,%2,%3}, [%4];"
                 : "=r"(r[0]), "=r"(r[1]), "=r"(r[2]), "=r"(r[3]) : "r"(a));
}
__device__ __forceinline__ void ldsm2(uint32_t* r, uint32_t a) {
    asm volatile("ldmatrix.sync.aligned.m8n8.x2.shared.b16 {%0,%1}, [%2];"
                 : "=r"(r[0]), "=r"(r[1]) : "r"(a));
}
__device__ __forceinline__ void mma16816(float* c, const uint32_t* a,
                                         const uint32_t* b) {
    asm volatile("mma.sync.aligned.m16n8k16.row.col.f32.bf16.bf16.f32 "
                 "{%0,%1,%2,%3}, {%4,%5,%6,%7}, {%8,%9}, {%0,%1,%2,%3};"
                 : "+f"(c[0]), "+f"(c[1]), "+f"(c[2]), "+f"(c[3])
                 : "r"(a[0]), "r"(a[1]), "r"(a[2]), "r"(a[3]),
                   "r"(b[0]), "r"(b[1]));
}

// ---------------- bf16 3-way exact split ----------------
__device__ __forceinline__ void split3(float v, __nv_bfloat16& b0,
                                       __nv_bfloat16& b1, __nv_bfloat16& b2) {
    b0 = __float2bfloat16(v);
    float f0 = __bfloat162float(b0);
    b1 = __float2bfloat16(v - f0);
    float f1 = __bfloat162float(b1);
    b2 = __float2bfloat16(v - f0 - f1);
}

__global__ void k_split_A(const float* __restrict__ A) {
    __shared__ float tile[32][33];
    int tx = threadIdx.x, ty = threadIdx.y;
    int kbase = blockIdx.y * 32, nbase = blockIdx.x * 32;
    #pragma unroll
    for (int i = 0; i < 32; i += 8)
        tile[ty + i][tx] = A[(size_t)(kbase + ty + i) * H_ + nbase + tx];
    __syncthreads();
    #pragma unroll
    for (int i = 0; i < 32; i += 8) {
        float v = tile[tx][ty + i];
        size_t o = (size_t)(nbase + ty + i) * H_ + kbase + tx;
        __nv_bfloat16 b0, b1, b2; split3(v, b0, b1, b2);
        gA0[o] = b0; gA1[o] = b1; gA2[o] = b2;
    }
}

// ------- input GEMM: fp32, ascending-k FFMA (bit-identical, round-9) -------
__global__ void __launch_bounds__(256) k_input_gemm(
    const float* __restrict__ X, const float* __restrict__ W,
    const float* __restrict__ bias)
{
    constexpr int K = NIN, N = H_;
    constexpr int BM = 128, BN = 128, BK = 16, TM = 8, TN = 8;
    __shared__ __align__(16) float As[2][BM][BK];
    __shared__ __align__(16) float Bs[2][BK][BN];

    const int tid = threadIdx.x;
    const int bm = blockIdx.y, bn = blockIdx.x;
    const int tRow = (tid >> 4) << 3, tCol = (tid & 15) << 3;
    const int m0g = bm * BM, n0g = bn * BN;

    auto load_stage = [&](int buf, int k0) {
        #pragma unroll
        for (int h = 0; h < 2; h++) {
            int c = tid + h * 256;
            int ar = c >> 2, aj = (c & 3) * 4;
            cpa16_z(smem_u32(&As[buf][ar][aj]),
                    X + (size_t)(m0g + ar) * K + k0 + aj, (k0 + aj) < K);
            int brw = c >> 5, bc = (c & 31) * 4;
            cpa16_z(smem_u32(&Bs[buf][brw][bc]),
                    W + (size_t)(k0 + brw) * N + n0g + bc, (k0 + brw) < K);
        }
    };

    float acc[TM][TN];
    #pragma unroll
    for (int i = 0; i < TM; i++)
        #pragma unroll
        for (int j = 0; j < TN; j++) acc[i][j] = 0.f;

    constexpr int NS = (K + BK - 1) / BK;   // 44
    load_stage(0, 0); CP_COMMIT();

    for (int s = 0; s < NS; s++) {
        int buf = s & 1;
        __syncthreads();
        if (s + 1 < NS) { load_stage(buf ^ 1, (s + 1) * BK); CP_COMMIT(); CP_WAIT1(); }
        else CP_WAIT0();
        __syncthreads();

        #pragma unroll
        for (int k = 0; k < BK; k++) {
            float aF[TM], bF[TN];
            #pragma unroll
            for (int i = 0; i < TM; i++) aF[i] = As[buf][tRow + i][k];
            float4 b0 = *(const float4*)&Bs[buf][k][tCol];
            float4 b1 = *(const float4*)&Bs[buf][k][tCol + 4];
            bF[0] = b0.x; bF[1] = b0.y; bF[2] = b0.z; bF[3] = b0.w;
            bF[4] = b1.x; bF[5] = b1.y; bF[6] = b1.z; bF[7] = b1.w;
            #pragma unroll
            for (int i = 0; i < TM; i++)
                #pragma unroll
                for (int j = 0; j < TN; j++) acc[i][j] += aF[i] * bF[j];
        }
    }

    const int m0 = m0g + tRow, n0 = n0g + tCol;
    #pragma unroll
    for (int i = 0; i < TM; i++) {
        size_t row = (size_t)(m0 + i) * N;
        #pragma unroll
        for (int j = 0; j < TN; j++)
            g_U[row + n0 + j] = 0.5f * (acc[i][j] + bias[n0 + j]);
    }
}

// ---------------- frame 0 (spike0 = 0 -> r = 0) ----------------
__global__ void k_frame0(const float* __restrict__ mem_init,
                         float* __restrict__ out_mems,
                         float* __restrict__ out_spikes)
{
    size_t idx = (size_t)blockIdx.x * 256 + threadIdx.x;
    int b = (int)(idx / H_), n = (int)(idx % H_);
    size_t o = ((size_t)b * T_) * H_ + n;
    float u = g_U[o];
    float y = tanhf(u);
    float mem = mem_init[idx] * 0.5f - 0.5f * (1.0f - 0.0f) + y;
    float sp = (mem > 0.5f) ? 1.0f : 0.0f;
    out_mems[o] = mem;
    out_spikes[o] = sp;
    gS[0][idx] = __float2bfloat16(sp);
}

// ==== persistent frames kernel: t = 1..127 in ONE launch ====================
// Body per frame = round-11 verbatim (BK=64 stages, 3-ring, 1 barrier/stage;
// per-BK=32-chunk mma chain + IEEE fold -> bit-identical). mem/spike state is
// carried in registers; inter-frame dependency enforced with per-bm-group
// (32 CTA) device barriers. All 128 CTAs are co-resident (1 CTA/SM).
#define SPD2 72
#define TSZ  (64 * SPD2)
#define STG  (4 * TSZ)
#define FR_SMEM_B (3 * STG * 2)          // 110592 B

__global__ void __launch_bounds__(256)
k_frames(float* __restrict__ out_mems, float* __restrict__ out_spikes)
{
    extern __shared__ __align__(16) __nv_bfloat16 smf[];
    const int tid = threadIdx.x;
    const int lane = tid & 31, w = tid >> 5;
    const int wm = w & 1, wn = w >> 1;               // warp tile 32(m) x 16(n)
    const int l15 = lane & 15;
    const int n0 = blockIdx.x * 64, m0 = blockIdx.y * 64;
    const int bm = blockIdx.y;

    const __nv_bfloat16* Ap[3] = { gA0 + (size_t)n0 * H_,
                                   gA1 + (size_t)n0 * H_,
                                   gA2 + (size_t)n0 * H_ };

    const int gq = lane >> 2, tq = lane & 3;
    // per-thread element coordinates (16 elems), fixed across frames
    int eb[2][2], en[2][2][2];
    #pragma unroll
    for (int mi = 0; mi < 2; mi++)
        #pragma unroll
        for (int h = 0; h < 2; h++)
            eb[mi][h] = m0 + wm * 32 + mi * 16 + gq + h * 8;
    #pragma unroll
    for (int ni = 0; ni < 2; ni++)
        #pragma unroll
        for (int e = 0; e < 2; e++)
            en[ni][0][e] = n0 + wn * 16 + ni * 8 + tq * 2 + e;

    // carry registers: mem of previous frame for my 16 elements (init = frame 0)
    float memc[2][2][2][2];
    #pragma unroll
    for (int mi = 0; mi < 2; mi++)
        #pragma unroll
        for (int ni = 0; ni < 2; ni++)
            #pragma unroll
            for (int h = 0; h < 2; h++)
                #pragma unroll
                for (int e = 0; e < 2; e++)
                    memc[mi][ni][h][e] =
                        out_mems[((size_t)eb[mi][h] * T_) * H_ + en[ni][0][e]];

    const int a_row = wm * 32 + l15;
    const int b_rb  = wn * 16 + (l15 & 7);
    const int a_co  = (lane >> 4) * 8;
    const int b_co  = ((l15 >> 3) & 1) * 8;

    for (int t = 1; t < T_; t++) {
        // wait for frame t-1 rows [m0, m0+64) (group bm), except t=1 (prev launch)
        if (t >= 2) {
            if (tid == 0)
                while (atomicAdd(&gCnt[t - 1][bm], 0u) < 32u) __nanosleep(64);
            __syncthreads();
        }

        const __nv_bfloat16* Sg = gS[(t + 1) & 1];

        auto load_stage = [&](int buf, int k0) {
            __nv_bfloat16* st = smf + (size_t)buf * STG;
            #pragma unroll
            for (int i = 0; i < 8; i++) {
                int c = tid + i * 256;
                int tile = c >> 9;
                int r = (c >> 3) & 63;
                int j = (c & 7) * 8;
                const __nv_bfloat16* src = (tile == 0)
                    ? Sg + (size_t)(m0 + r) * H_ + k0 + j
                    : Ap[tile - 1] + (size_t)r * H_ + k0 + j;
                cpa16(smem_u32(st + tile * TSZ + r * SPD2 + j), src);
            }
        };

        float master[2][2][4];
        #pragma unroll
        for (int a = 0; a < 2; a++)
            #pragma unroll
            for (int b = 0; b < 2; b++)
                #pragma unroll
                for (int c = 0; c < 4; c++) master[a][b][c] = 0.f;

        load_stage(0, 0);  CP_COMMIT();
        load_stage(1, 64); CP_COMMIT();

        constexpr int NS = H_ / 64;     // 32 stages, BK=64 (2 x BK=32 chunks)
        for (int s = 0; s < NS; s++) {
            int buf = s % 3;
            CP_WAIT1();
            __syncthreads();
            if (s + 2 < NS) load_stage((s + 2) % 3, (s + 2) * 64);
            CP_COMMIT();

            uint32_t sb = smem_u32(smf + (size_t)buf * STG);
            #pragma unroll
            for (int c32 = 0; c32 < 2; c32++) {
                const uint32_t kbyte = (uint32_t)c32 * 64;

                float tacc[2][2][4];
                #pragma unroll
                for (int a = 0; a < 2; a++)
                    #pragma unroll
                    for (int b = 0; b < 2; b++)
                        #pragma unroll
                        for (int c = 0; c < 4; c++) tacc[a][b][c] = 0.f;

                #pragma unroll
                for (int kk = 0; kk < 2; kk++) {
                    uint32_t af[2][4];
                    #pragma unroll
                    for (int mi = 0; mi < 2; mi++) {
                        int row = a_row + mi * 16;
                        ldsm4(af[mi], sb + (uint32_t)((row * SPD2 + a_co) * 2
                                                      + kbyte + kk * 32));
                    }
                    #pragma unroll
                    for (int p = 0; p < 3; p++) {
                        uint32_t ab = sb + (uint32_t)((1 + p) * TSZ * 2);
                        #pragma unroll
                        for (int ni = 0; ni < 2; ni++) {
                            uint32_t bfr[2];
                            int row = b_rb + ni * 8;
                            ldsm2(bfr, ab + (uint32_t)((row * SPD2 + b_co) * 2
                                                       + kbyte + kk * 32));
                            mma16816(tacc[0][ni], af[0], bfr);
                            mma16816(tacc[1][ni], af[1], bfr);
                        }
                    }
                }
                #pragma unroll
                for (int a = 0; a < 2; a++)
                    #pragma unroll
                    for (int b = 0; b < 2; b++)
                        #pragma unroll
                        for (int c = 0; c < 4; c++)
                            master[a][b][c] += tacc[a][b][c];
            }
        }

        // fused epilogue — arithmetic identical to round 11, state from registers
        __nv_bfloat16* Sout = gS[t & 1];
        #pragma unroll
        for (int mi = 0; mi < 2; mi++)
            #pragma unroll
            for (int ni = 0; ni < 2; ni++)
                #pragma unroll
                for (int h = 0; h < 2; h++)
                    #pragma unroll
                    for (int e = 0; e < 2; e++) {
                        int b = eb[mi][h];
                        int n = en[ni][0][e];
                        size_t o = ((size_t)b * T_ + t) * H_ + n;
                        float u = __ldcs(&g_U[o]);
                        float mem_prev = memc[mi][ni][h][e];
                        float sp_prev = (mem_prev > 0.5f) ? 1.0f : 0.0f;
                        float y = tanhf(0.5f * master[mi][ni][h * 2 + e] + u);
                        float mem = mem_prev * 0.5f - 0.5f * (1.0f - sp_prev) + y;
                        float sp = (mem > 0.5f) ? 1.0f : 0.0f;
                        __stcs(&out_mems[o], mem);
                        __stcs(&out_spikes[o], sp);
                        Sout[(size_t)b * H_ + n] = __float2bfloat16(sp);
                        memc[mi][ni][h][e] = mem;
                    }

        // publish frame t to group bm
        __threadfence();
        __syncthreads();
        if (tid == 0 && t < T_ - 1) atomicAdd(&gCnt[t][bm], 1u);
    }
}

// ----------------------------------------------------------------------------
extern "C" void kernel_launch(void* const* d_in, const int* in_sizes, int n_in,
                              void* d_out, int out_size)
{
    const float* x        = (const float*)d_in[0];
    const float* W_in     = (const float*)d_in[1];
    const float* Arec     = (const float*)d_in[2];
    const float* bias     = (const float*)d_in[3];
    const float* mem_init = (const float*)d_in[4];

    float* out        = (float*)d_out;
    float* out_mems   = out;
    float* out_spikes = out + (size_t)B_ * T_ * H_;

    cudaFuncSetAttribute(k_frames,
                         cudaFuncAttributeMaxDynamicSharedMemorySize, FR_SMEM_B);

    // zero the group-barrier counters (captured as a graph memset node)
    void* cnt_addr = nullptr;
    cudaGetSymbolAddress(&cnt_addr, gCnt);
    cudaMemsetAsync(cnt_addr, 0, sizeof(unsigned) * T_ * 4);

    { dim3 g(H_ / 32, H_ / 32), b(32, 8); k_split_A<<<g, b>>>(Arec); }
    { dim3 g(H_ / 128, (B_ * T_) / 128); k_input_gemm<<<g, 256>>>(x, W_in, bias); }

    k_frame0<<<(B_ * H_) / 256, 256>>>(mem_init, out_mems, out_spikes);

    dim3 g(H_ / 64, B_ / 64);     // (32, 4) = 128 CTAs, all co-resident
    k_frames<<<g, 256, FR_SMEM_B>>>(out_mems, out_spikes);
}